// round 3
// baseline (speedup 1.0000x reference)
#include <cuda_runtime.h>
#include <math.h>

#define B_     8
#define CIN_   512
#define COUT_  512
#define SDIM_  512
#define RES_   64

#define AFF_SCALE   0.04419417382415922f    /* 1/sqrt(512)  */
#define CONV_SCALE  0.014731391274719738f   /* 1/sqrt(4608) */
#define LRELU_GAIN  1.4142135623730951f

#define CO_T 32
#define H_T  8
#define CI_T 8

/* scratch (allocation-free: __device__ globals) */
__device__ float g_style[B_ * CIN_];
__device__ float g_wsq[COUT_ * CIN_];
__device__ float g_d[B_ * COUT_];

/* ---- style[b,c] = sum_s w[b,s]*affine_w[c,s]*AFF_SCALE + affine_b[c] ---- */
__global__ __launch_bounds__(256)
void style_kernel(const float* __restrict__ w,
                  const float* __restrict__ aw,
                  const float* __restrict__ ab) {
    int wid  = blockIdx.x * (blockDim.x >> 5) + (threadIdx.x >> 5);
    int lane = threadIdx.x & 31;
    if (wid >= B_ * CIN_) return;
    int b = wid / CIN_;
    int c = wid % CIN_;
    const float* wr = w  + b * SDIM_;
    const float* ar = aw + c * SDIM_;
    float s = 0.f;
    #pragma unroll 4
    for (int k = lane; k < SDIM_; k += 32) s += wr[k] * ar[k];
    #pragma unroll
    for (int o = 16; o; o >>= 1) s += __shfl_xor_sync(0xffffffffu, s, o);
    if (lane == 0) g_style[wid] = s * AFF_SCALE + ab[c];
}

/* ---- wsq[co,ci] = sum_k conv_w[co,ci,k]^2 ---- */
__global__ __launch_bounds__(256)
void wsq_kernel(const float* __restrict__ cw) {
    int i = blockIdx.x * blockDim.x + threadIdx.x;
    if (i >= COUT_ * CIN_) return;
    const float* p = cw + (long)i * 9;
    float s = 0.f;
    #pragma unroll
    for (int k = 0; k < 9; k++) s += p[k] * p[k];
    g_wsq[i] = s;
}

/* ---- d[b,co] = rsqrt(CONV_SCALE^2 * sum_ci wsq[co,ci]*style[b,ci]^2 + 1e-8) ---- */
__global__ __launch_bounds__(256)
void demod_kernel() {
    int wid  = blockIdx.x * (blockDim.x >> 5) + (threadIdx.x >> 5);
    int lane = threadIdx.x & 31;
    if (wid >= B_ * COUT_) return;
    int b  = wid / COUT_;
    int co = wid % COUT_;
    float s = 0.f;
    #pragma unroll 4
    for (int ci = lane; ci < CIN_; ci += 32) {
        float st = g_style[b * CIN_ + ci];
        s += g_wsq[co * CIN_ + ci] * st * st;
    }
    #pragma unroll
    for (int o = 16; o; o >>= 1) s += __shfl_xor_sync(0xffffffffu, s, o);
    if (lane == 0)
        g_d[wid] = rsqrtf(s * (CONV_SCALE * CONV_SCALE) + 1e-8f);
}

/* ---- fused modulated 3x3 conv + noise + bias + lrelu*sqrt(2) ----
 * grid: (RES/H_T=8, COUT/CO_T=16, B=8); block: 256
 * thread: tco = tid/64 (0..3), tsp = tid%64 (column)
 * register tile: acc[8 co][8 rows] at column tsp
 */
__global__ __launch_bounds__(256)
void conv_kernel(const float* __restrict__ x,
                 const float* __restrict__ cw,
                 const float* __restrict__ noise,
                 const float* __restrict__ noise_scale,
                 const float* __restrict__ bias,
                 float* __restrict__ out) {
    __shared__ float xs[CI_T][H_T + 2][RES_ + 2];  /* 21120 B */
    __shared__ float ws[CI_T][9][CO_T];            /*  9216 B */

    const int tid  = threadIdx.x;
    const int tco  = tid >> 6;   /* 0..3  */
    const int tsp  = tid & 63;   /* 0..63 */
    const int b    = blockIdx.z;
    const int co0  = blockIdx.y * CO_T;
    const int row0 = blockIdx.x * H_T;

    float acc[8][8];
    #pragma unroll
    for (int i = 0; i < 8; i++)
        #pragma unroll
        for (int j = 0; j < 8; j++) acc[i][j] = 0.f;

    #pragma unroll 1
    for (int ci0 = 0; ci0 < CIN_; ci0 += CI_T) {
        /* stage x tile (with zero halo) */
        #pragma unroll 1
        for (int idx = tid; idx < CI_T * (H_T + 2) * RES_; idx += 256) {
            int col = idx & 63;
            int r   = (idx >> 6) % (H_T + 2);
            int ci  = idx / (64 * (H_T + 2));
            int grow = row0 + r - 1;
            float v = 0.f;
            if (grow >= 0 && grow < RES_)
                v = x[(((long)(b * CIN_ + ci0 + ci) * RES_) + grow) * RES_ + col];
            xs[ci][r][col + 1] = v;
        }
        if (tid < CI_T * (H_T + 2)) {
            int r  = tid % (H_T + 2);
            int ci = tid / (H_T + 2);
            xs[ci][r][0]        = 0.f;
            xs[ci][r][RES_ + 1] = 0.f;
        }
        /* stage style-modulated weights */
        #pragma unroll 1
        for (int idx = tid; idx < CO_T * CI_T * 9; idx += 256) {
            int k  = idx % 9;
            int ci = (idx / 9) % CI_T;
            int co = idx / (9 * CI_T);
            float s = g_style[b * CIN_ + ci0 + ci] * CONV_SCALE;
            ws[ci][k][co] = cw[((long)(co0 + co) * CIN_ + (ci0 + ci)) * 9 + k] * s;
        }
        __syncthreads();

        #pragma unroll 1
        for (int ci = 0; ci < CI_T; ci++) {
            #pragma unroll
            for (int kh = 0; kh < 3; kh++) {
                #pragma unroll
                for (int kw = 0; kw < 3; kw++) {
                    float wv[8], xv[8];
                    #pragma unroll
                    for (int i = 0; i < 8; i++) wv[i] = ws[ci][kh * 3 + kw][tco * 8 + i];
                    #pragma unroll
                    for (int j = 0; j < 8; j++) xv[j] = xs[ci][j + kh][tsp + kw];
                    #pragma unroll
                    for (int i = 0; i < 8; i++)
                        #pragma unroll
                        for (int j = 0; j < 8; j++)
                            acc[i][j] = fmaf(wv[i], xv[j], acc[i][j]);
                }
            }
        }
        __syncthreads();
    }

    /* epilogue: demod scale, noise, bias, lrelu * sqrt(2) */
    const float nsc = *noise_scale;
    float dv[8], bv[8];
    #pragma unroll
    for (int i = 0; i < 8; i++) {
        int co = co0 + tco * 8 + i;
        dv[i] = g_d[b * COUT_ + co];
        bv[i] = bias[co];
    }
    #pragma unroll
    for (int j = 0; j < 8; j++) {
        int row = row0 + j;
        float nz = noise[(b * RES_ + row) * RES_ + tsp] * nsc;
        #pragma unroll
        for (int i = 0; i < 8; i++) {
            int co = co0 + tco * 8 + i;
            float v = acc[i][j] * dv[i] + nz + bv[i];
            v = (v > 0.f ? v : 0.2f * v) * LRELU_GAIN;
            out[(((long)(b * COUT_ + co) * RES_) + row) * RES_ + tsp] = v;
        }
    }
}

extern "C" void kernel_launch(void* const* d_in, const int* in_sizes, int n_in,
                              void* d_out, int out_size) {
    const float* x     = (const float*)d_in[0];
    const float* w     = (const float*)d_in[1];
    const float* noise = (const float*)d_in[2];
    const float* aw    = (const float*)d_in[3];
    const float* ab    = (const float*)d_in[4];
    const float* cw    = (const float*)d_in[5];
    const float* ns    = (const float*)d_in[6];
    const float* bias  = (const float*)d_in[7];
    float* out = (float*)d_out;

    style_kernel<<<512, 256>>>(w, aw, ab);      /* 4096 warps: one per (b,c) */
    wsq_kernel<<<1024, 256>>>(cw);              /* 262144 threads             */
    demod_kernel<<<512, 256>>>();               /* 4096 warps: one per (b,co) */

    dim3 grid(RES_ / H_T, COUT_ / CO_T, B_);    /* (8, 16, 8) */
    conv_kernel<<<grid, 256>>>(x, cw, noise, ns, bias, out);
}

// round 5
// speedup vs baseline: 1.2196x; 1.2196x over previous
#include <cuda_runtime.h>
#include <math.h>

#define B_     8
#define CIN_   512
#define COUT_  512
#define SDIM_  512
#define RES_   64

#define AFF_SCALE   0.04419417382415922f    /* 1/sqrt(512)  */
#define CONV_SCALE  0.014731391274719738f   /* 1/sqrt(4608) */
#define LRELU_GAIN  1.4142135623730951f

#define CO_T 32
#define H_T  8
#define CI_T 8

/* scratch (allocation-free: __device__ globals) */
__device__ float g_style[B_ * CIN_];
__device__ float g_wsq[COUT_ * CIN_];
__device__ float g_d[B_ * COUT_];

/* ---- packed f32x2 helpers (FFMA2 path ptxas won't emit from C++) ---- */
__device__ __forceinline__ unsigned long long ffma2(unsigned long long a,
                                                    unsigned long long b,
                                                    unsigned long long c) {
    unsigned long long d;
    asm("fma.rn.f32x2 %0, %1, %2, %3;" : "=l"(d) : "l"(a), "l"(b), "l"(c));
    return d;
}
__device__ __forceinline__ unsigned long long pack_dup(float x) {
    unsigned long long d;
    asm("mov.b64 %0, {%1, %1};" : "=l"(d) : "f"(x));
    return d;
}
__device__ __forceinline__ void unpack2(unsigned long long v, float& lo, float& hi) {
    asm("mov.b64 {%0, %1}, %2;" : "=f"(lo), "=f"(hi) : "l"(v));
}

/* ---- style[b,c] = sum_s w[b,s]*affine_w[c,s]*AFF_SCALE + affine_b[c] ---- */
__global__ __launch_bounds__(256)
void style_kernel(const float* __restrict__ w,
                  const float* __restrict__ aw,
                  const float* __restrict__ ab) {
    int wid  = blockIdx.x * (blockDim.x >> 5) + (threadIdx.x >> 5);
    int lane = threadIdx.x & 31;
    if (wid >= B_ * CIN_) return;
    int b = wid / CIN_;
    int c = wid % CIN_;
    const float* wr = w  + b * SDIM_;
    const float* ar = aw + c * SDIM_;
    float s = 0.f;
    #pragma unroll 4
    for (int k = lane; k < SDIM_; k += 32) s += wr[k] * ar[k];
    #pragma unroll
    for (int o = 16; o; o >>= 1) s += __shfl_xor_sync(0xffffffffu, s, o);
    if (lane == 0) g_style[wid] = s * AFF_SCALE + ab[c];
}

/* ---- wsq[co,ci] = sum_k conv_w[co,ci,k]^2 ---- */
__global__ __launch_bounds__(256)
void wsq_kernel(const float* __restrict__ cw) {
    int i = blockIdx.x * blockDim.x + threadIdx.x;
    if (i >= COUT_ * CIN_) return;
    const float* p = cw + (long)i * 9;
    float s = 0.f;
    #pragma unroll
    for (int k = 0; k < 9; k++) s += p[k] * p[k];
    g_wsq[i] = s;
}

/* ---- d[b,co] = rsqrt(CONV_SCALE^2 * sum_ci wsq[co,ci]*style[b,ci]^2 + 1e-8) ---- */
__global__ __launch_bounds__(256)
void demod_kernel() {
    int wid  = blockIdx.x * (blockDim.x >> 5) + (threadIdx.x >> 5);
    int lane = threadIdx.x & 31;
    if (wid >= B_ * COUT_) return;
    int b  = wid / COUT_;
    int co = wid % COUT_;
    float s = 0.f;
    #pragma unroll 4
    for (int ci = lane; ci < CIN_; ci += 32) {
        float st = g_style[b * CIN_ + ci];
        s += g_wsq[co * CIN_ + ci] * st * st;
    }
    #pragma unroll
    for (int o = 16; o; o >>= 1) s += __shfl_xor_sync(0xffffffffu, s, o);
    if (lane == 0)
        g_d[wid] = rsqrtf(s * (CONV_SCALE * CONV_SCALE) + 1e-8f);
}

/* ---- fused modulated 3x3 conv + noise + bias + lrelu*sqrt(2) ----
 * grid: (RES/H_T=8, COUT/CO_T=16, B=8); block: 256
 * thread: tco = tid/64 (0..3), tsp = tid%64 (column)
 * packed tile: accp[4 co-pairs][8 rows] (f32x2), co pair = co0+tco*8+2*ip+{0,1}
 */
__global__ __launch_bounds__(256, 2)
void conv_kernel(const float* __restrict__ x,
                 const float* __restrict__ cw,
                 const float* __restrict__ noise,
                 const float* __restrict__ noise_scale,
                 const float* __restrict__ bias,
                 float* __restrict__ out) {
    __shared__ __align__(16) float xs[CI_T][H_T + 2][RES_ + 2];  /* 21120 B */
    __shared__ __align__(16) float ws[CI_T][9][CO_T];            /*  9216 B */

    const int tid  = threadIdx.x;
    const int tco  = tid >> 6;   /* 0..3  */
    const int tsp  = tid & 63;   /* 0..63 */
    const int b    = blockIdx.z;
    const int co0  = blockIdx.y * CO_T;
    const int row0 = blockIdx.x * H_T;

    unsigned long long accp[4][8];
    #pragma unroll
    for (int i = 0; i < 4; i++)
        #pragma unroll
        for (int j = 0; j < 8; j++) accp[i][j] = 0ull;

    #pragma unroll 1
    for (int ci0 = 0; ci0 < CIN_; ci0 += CI_T) {
        /* stage x tile (with zero halo) */
        #pragma unroll 1
        for (int idx = tid; idx < CI_T * (H_T + 2) * RES_; idx += 256) {
            int col = idx & 63;
            int r   = (idx >> 6) % (H_T + 2);
            int ci  = idx / (64 * (H_T + 2));
            int grow = row0 + r - 1;
            float v = 0.f;
            if (grow >= 0 && grow < RES_)
                v = x[(((long)(b * CIN_ + ci0 + ci) * RES_) + grow) * RES_ + col];
            xs[ci][r][col + 1] = v;
        }
        if (tid < CI_T * (H_T + 2)) {
            int r  = tid % (H_T + 2);
            int ci = tid / (H_T + 2);
            xs[ci][r][0]        = 0.f;
            xs[ci][r][RES_ + 1] = 0.f;
        }
        /* stage style-modulated weights */
        #pragma unroll 1
        for (int idx = tid; idx < CO_T * CI_T * 9; idx += 256) {
            int k  = idx % 9;
            int ci = (idx / 9) % CI_T;
            int co = idx / (9 * CI_T);
            float s = g_style[b * CIN_ + ci0 + ci] * CONV_SCALE;
            ws[ci][k][co] = cw[((long)(co0 + co) * CIN_ + (ci0 + ci)) * 9 + k] * s;
        }
        __syncthreads();

        #pragma unroll 1
        for (int ci = 0; ci < CI_T; ci++) {
            #pragma unroll
            for (int kh = 0; kh < 3; kh++) {
                #pragma unroll
                for (int kw = 0; kw < 3; kw++) {
                    /* x values for 8 rows, duplicated into both packed lanes */
                    unsigned long long xx[8];
                    #pragma unroll
                    for (int j = 0; j < 8; j++)
                        xx[j] = pack_dup(xs[ci][j + kh][tsp + kw]);
                    /* 4 co-pairs of weights: one aligned LDS.64 each */
                    unsigned long long wp[4];
                    #pragma unroll
                    for (int ip = 0; ip < 4; ip++)
                        wp[ip] = *(const unsigned long long*)
                                 &ws[ci][kh * 3 + kw][tco * 8 + 2 * ip];
                    #pragma unroll
                    for (int ip = 0; ip < 4; ip++)
                        #pragma unroll
                        for (int j = 0; j < 8; j++)
                            accp[ip][j] = ffma2(wp[ip], xx[j], accp[ip][j]);
                }
            }
        }
        __syncthreads();
    }

    /* epilogue: demod scale, noise, bias, lrelu * sqrt(2) */
    const float nsc = *noise_scale;
    float dv[8], bv[8];
    #pragma unroll
    for (int i = 0; i < 8; i++) {
        int co = co0 + tco * 8 + i;
        dv[i] = g_d[b * COUT_ + co];
        bv[i] = bias[co];
    }
    #pragma unroll
    for (int j = 0; j < 8; j++) {
        int row = row0 + j;
        float nz = noise[(b * RES_ + row) * RES_ + tsp] * nsc;
        #pragma unroll
        for (int ip = 0; ip < 4; ip++) {
            float a0, a1;
            unpack2(accp[ip][j], a0, a1);
            int i0 = 2 * ip, i1 = 2 * ip + 1;
            int coA = co0 + tco * 8 + i0;
            int coB = co0 + tco * 8 + i1;
            float v0 = a0 * dv[i0] + nz + bv[i0];
            float v1 = a1 * dv[i1] + nz + bv[i1];
            v0 = (v0 > 0.f ? v0 : 0.2f * v0) * LRELU_GAIN;
            v1 = (v1 > 0.f ? v1 : 0.2f * v1) * LRELU_GAIN;
            out[(((long)(b * COUT_ + coA) * RES_) + row) * RES_ + tsp] = v0;
            out[(((long)(b * COUT_ + coB) * RES_) + row) * RES_ + tsp] = v1;
        }
    }
}

extern "C" void kernel_launch(void* const* d_in, const int* in_sizes, int n_in,
                              void* d_out, int out_size) {
    const float* x     = (const float*)d_in[0];
    const float* w     = (const float*)d_in[1];
    const float* noise = (const float*)d_in[2];
    const float* aw    = (const float*)d_in[3];
    const float* ab    = (const float*)d_in[4];
    const float* cw    = (const float*)d_in[5];
    const float* ns    = (const float*)d_in[6];
    const float* bias  = (const float*)d_in[7];
    float* out = (float*)d_out;

    style_kernel<<<512, 256>>>(w, aw, ab);      /* 4096 warps: one per (b,c) */
    wsq_kernel<<<1024, 256>>>(cw);              /* 262144 threads             */
    demod_kernel<<<512, 256>>>();               /* 4096 warps: one per (b,co) */

    dim3 grid(RES_ / H_T, COUT_ / CO_T, B_);    /* (8, 16, 8) */
    conv_kernel<<<grid, 256>>>(x, cw, noise, ns, bias, out);
}